// round 2
// baseline (speedup 1.0000x reference)
#include <cuda_runtime.h>
#include <cstddef>

#define B_   2
#define N_   768
#define BN_  1536
#define D_   512
#define E_   64
#define LN_EPS 1e-5f
#define PADR 68               // 64 + 4 pad floats (float4-aligned: 68*4B=272B=17 float4)

// ---------------- scratch ----------------
__device__ float g_WR[D_ * E_];     // fused W_edges@W_rows, [d][f]
__device__ float g_WC[D_ * E_];     // fused W_edges@W_cols, [d][f]
__device__ float g_Rc[BN_ * E_];    // centered R' = R - mean(R)
__device__ float g_Cc[BN_ * E_];    // centered C'
__device__ float g_varR[BN_];
__device__ float g_varC[BN_];

// ---------------- kernel A: WR[d][f] = sum_e W_edges[f][e] * W_rows[e][d] ----
__global__ void kA(const float* __restrict__ We,
                   const float* __restrict__ Wr,
                   const float* __restrict__ Wc) {
    int idx = blockIdx.x * 256 + threadIdx.x;   // 0 .. 32767
    int f = idx >> 9;
    int d = idx & 511;
    float ar = 0.f, ac = 0.f;
#pragma unroll 8
    for (int e = 0; e < E_; e++) {
        float we = We[f * E_ + e];
        ar = fmaf(we, Wr[e * D_ + d], ar);
        ac = fmaf(we, Wc[e * D_ + d], ac);
    }
    g_WR[d * E_ + f] = ar;
    g_WC[d * E_ + f] = ac;
}

// ---------------- kernel B: row GEMM + center + variance, fused --------------
// grid 384, block 256. Each block: 4 rows, full K=512.
// f = tid&63, g = tid>>6 (row within tile). Group g = warps {2g, 2g+1}.
__global__ void kB(const float* __restrict__ x) {
    __shared__ float xs[4 * D_];
    __shared__ float red[8][4];
    int row0 = blockIdx.x * 4;
    int tid  = threadIdx.x;

    for (int idx = tid; idx < 4 * D_; idx += 256)
        xs[idx] = x[(size_t)row0 * D_ + idx];
    __syncthreads();

    int f = tid & 63;
    int g = tid >> 6;
    const float* xp = xs + g * D_;
    float aR = 0.f, aC = 0.f;
#pragma unroll 8
    for (int dd = 0; dd < D_; dd++) {
        float xv = xp[dd];
        aR = fmaf(xv, g_WR[dd * E_ + f], aR);
        aC = fmaf(xv, g_WC[dd * E_ + f], aC);
    }

    // reduce sum/sumsq over the 64 f-lanes of this row (2 warps)
    float s0 = aR, s1 = aR * aR, s2 = aC, s3 = aC * aC;
#pragma unroll
    for (int o = 16; o; o >>= 1) {
        s0 += __shfl_xor_sync(0xffffffffu, s0, o);
        s1 += __shfl_xor_sync(0xffffffffu, s1, o);
        s2 += __shfl_xor_sync(0xffffffffu, s2, o);
        s3 += __shfl_xor_sync(0xffffffffu, s3, o);
    }
    int w = tid >> 5;
    if ((tid & 31) == 0) { red[w][0] = s0; red[w][1] = s1; red[w][2] = s2; red[w][3] = s3; }
    __syncthreads();

    int gw = g * 2;
    float sR  = red[gw][0] + red[gw + 1][0];
    float sRR = red[gw][1] + red[gw + 1][1];
    float sC  = red[gw][2] + red[gw + 1][2];
    float sCC = red[gw][3] + red[gw + 1][3];
    float mR = sR * (1.f / 64.f);
    float mC = sC * (1.f / 64.f);
    int row = row0 + g;
    g_Rc[row * E_ + f] = aR - mR;
    g_Cc[row * E_ + f] = aC - mC;
    if (f == 0) {
        g_varR[row] = sRR * (1.f / 64.f) - mR * mR;
        g_varC[row] = sCC * (1.f / 64.f) - mC * mC;
    }
}

// ---------------- kernel C: fused inv-std + streaming epilogue ---------------
// grid (48, 48, 2), block 256. Tile = 16 i x 16 j.
// Phase A: each thread computes one (ii,jj) dot -> inv std into smem.
// Phase B: pure streaming, STG.128, no SHFL/MUFU in hot loop.
__global__ void __launch_bounds__(256, 4) kC(const float* __restrict__ gamma,
                                             const float* __restrict__ beta,
                                             float* __restrict__ out) {
    __shared__ float rs[16 * PADR];
    __shared__ float cs[16 * PADR];
    __shared__ float vR[16];
    __shared__ float vC[16];
    __shared__ float inv[256];

    int i0 = blockIdx.x * 16;
    int j0 = blockIdx.y * 16;
    int b  = blockIdx.z;
    int tid = threadIdx.x;
    int rowR = b * N_ + i0;
    int rowC = b * N_ + j0;

    for (int idx = tid; idx < 16 * E_; idx += 256) {
        int r = idx >> 6, f = idx & 63;
        rs[r * PADR + f] = g_Rc[(rowR + r) * E_ + f];
        cs[r * PADR + f] = g_Cc[(rowC + r) * E_ + f];
    }
    if (tid < 16)      vR[tid]      = g_varR[rowR + tid];
    else if (tid < 32) vC[tid - 16] = g_varC[rowC + tid - 16];
    __syncthreads();

    // ---- Phase A: one dot per thread ----
    {
        int ii = tid >> 4, jj = tid & 15;
        const float4* r4 = (const float4*)(rs + ii * PADR);
        const float4* c4 = (const float4*)(cs + jj * PADR);
        float d = 0.f;
#pragma unroll
        for (int k = 0; k < 16; k++) {
            float4 a = r4[k], c = c4[k];
            d = fmaf(a.x, c.x, d);
            d = fmaf(a.y, c.y, d);
            d = fmaf(a.z, c.z, d);
            d = fmaf(a.w, c.w, d);
        }
        float var = vR[ii] + vC[jj] + d * (2.f / 64.f);
        inv[tid] = rsqrtf(var + LN_EPS);
    }
    __syncthreads();

    // ---- Phase B: streaming stores ----
    int f4 = tid & 15;           // which float4 of the 64-vector
    int g  = tid >> 4;           // which i row (0..15)
    float4 r  = ((const float4*)(rs + g * PADR))[f4];
    float4 gm = ((const float4*)gamma)[f4];
    float4 bt = ((const float4*)beta)[f4];
    float4* outp = (float4*)out + ((size_t)(b * N_ + i0 + g) * N_ + j0) * 16 + f4;
    const float* invg = inv + g * 16;

#pragma unroll
    for (int jj = 0; jj < 16; jj++) {
        float4 c = ((const float4*)(cs + jj * PADR))[f4];
        float iv = invg[jj];
        float4 o;
        o.x = fmaf((r.x + c.x) * iv, gm.x, bt.x);
        o.y = fmaf((r.y + c.y) * iv, gm.y, bt.y);
        o.z = fmaf((r.z + c.z) * iv, gm.z, bt.z);
        o.w = fmaf((r.w + c.w) * iv, gm.w, bt.w);
        outp[(size_t)jj * 16] = o;
    }
}

// ---------------- launch -------------------------------------------------------
extern "C" void kernel_launch(void* const* d_in, const int* in_sizes, int n_in,
                              void* d_out, int out_size) {
    const float* x     = (const float*)d_in[0];  // [2,768,512]
    const float* Wr    = (const float*)d_in[1];  // [64,512]
    const float* Wc    = (const float*)d_in[2];  // [64,512]
    const float* We    = (const float*)d_in[3];  // [64,64]
    const float* gamma = (const float*)d_in[4];  // [64]
    const float* beta  = (const float*)d_in[5];  // [64]
    float* out = (float*)d_out;                  // [2,768,768,64] fp32

    kA<<<128, 256>>>(We, Wr, Wc);
    kB<<<BN_ / 4, 256>>>(x);
    kC<<<dim3(N_ / 16, N_ / 16, B_), 256>>>(gamma, beta, out);
}

// round 3
// speedup vs baseline: 1.5262x; 1.5262x over previous
#include <cuda_runtime.h>
#include <cstddef>
#include <cstdint>

#define B_   2
#define N_   768
#define BN_  1536
#define D_   512
#define E_   64
#define LN_EPS 1e-5f
#define PADR 68            // kC smem row pitch (floats), float4-aligned
#define XP   130           // kB x-tile pitch (floats), float2-aligned

typedef unsigned long long ull;

// ---------------- scratch ----------------
__device__ float g_WR[D_ * E_];     // fused W_edges@W_rows, [d][f]
__device__ float g_WC[D_ * E_];     // fused W_edges@W_cols, [d][f]
__device__ float g_Rc[BN_ * E_];    // centered R'
__device__ float g_Cc[BN_ * E_];    // centered C'
__device__ float g_varR[BN_];
__device__ float g_varC[BN_];

// -------- f32x2 helpers --------
__device__ __forceinline__ void ffma2(ull& d, ull a, ull b) {
    asm("fma.rn.f32x2 %0, %1, %2, %0;" : "+l"(d) : "l"(a), "l"(b));
}
__device__ __forceinline__ ull pack2(float x) {
    ull r; unsigned u = __float_as_uint(x);
    asm("mov.b64 %0, {%1, %1};" : "=l"(r) : "r"(u));
    return r;
}

// ---------------- kernel A: WR[d][f] = sum_e We[f][e] * Wr[e][d] -------------
// grid 256, block 128 — one thread per (f,d), high block count for latency.
__global__ void __launch_bounds__(128) kA(const float* __restrict__ We,
                                          const float* __restrict__ Wr,
                                          const float* __restrict__ Wc) {
    int idx = blockIdx.x * 128 + threadIdx.x;   // 0..32767
    int f = idx >> 9;
    int d = idx & 511;
    const float* wep = We + f * E_;
    float ar = 0.f, ac = 0.f;
#pragma unroll 16
    for (int e = 0; e < E_; e++) {
        float we = __ldg(wep + e);
        ar = fmaf(we, __ldg(Wr + e * D_ + d), ar);
        ac = fmaf(we, __ldg(Wc + e * D_ + d), ac);
    }
    g_WR[d * E_ + f] = ar;
    g_WC[d * E_ + f] = ac;
}

// ---------------- kernel B: row GEMM + center + variance, fully fused --------
// grid 96, block 256, dynamic smem 73856 B.
// Layout: xs[16][XP] (2080 floats), weights chunk wrs/wcs[128][64] (16384 floats),
// partial buffer P aliases the weight region after the last chunk.
// Warp w owns dd in [w*16, w*16+16) of each 128-dd chunk; lane = f-pair f2.
// Accumulators: 16 rows x {R,C} as packed f32x2.
extern __shared__ float sm_b[];
__global__ void __launch_bounds__(256) kB(const float* __restrict__ x) {
    float* xs  = sm_b;            // 2080 floats
    float* wrs = sm_b + 2080;     // 8192 floats
    float* wcs = wrs + 8192;      // 8192 floats
    float* P   = sm_b + 2080;     // alias: 16384 floats

    int tid  = threadIdx.x;
    int f2   = tid & 31;
    int w    = tid >> 5;
    int row0 = blockIdx.x * 16;

    ull aR[16], aC[16];
#pragma unroll
    for (int r = 0; r < 16; r++) { aR[r] = 0ULL; aC[r] = 0ULL; }

    for (int c = 0; c < 4; c++) {
        int d0 = c * 128;
        // weights chunk (contiguous): g_WR[d0*64 .. +8192)
        for (int idx = tid; idx < 2048; idx += 256) {
            ((float4*)wrs)[idx] = ((const float4*)(g_WR + d0 * E_))[idx];
            ((float4*)wcs)[idx] = ((const float4*)(g_WC + d0 * E_))[idx];
        }
        // x tile: 16 rows x 128 dd
        for (int idx = tid; idx < 1024; idx += 256) {
            int r = idx >> 6, dd2 = idx & 63;
            *(float2*)(xs + r * XP + dd2 * 2) =
                *(const float2*)(x + (size_t)(row0 + r) * D_ + d0 + dd2 * 2);
        }
        __syncthreads();

        int wbase = w * 16;
#pragma unroll
        for (int p = 0; p < 8; p++) {
            int dd = wbase + p * 2;
            ull wr0 = *(const ull*)(wrs + dd * E_ + 2 * f2);
            ull wr1 = *(const ull*)(wrs + (dd + 1) * E_ + 2 * f2);
            ull wc0 = *(const ull*)(wcs + dd * E_ + 2 * f2);
            ull wc1 = *(const ull*)(wcs + (dd + 1) * E_ + 2 * f2);
#pragma unroll
            for (int r = 0; r < 16; r++) {
                float2 xv = *(const float2*)(xs + r * XP + dd);
                ull x0 = pack2(xv.x);
                ull x1 = pack2(xv.y);
                ffma2(aR[r], x0, wr0);
                ffma2(aR[r], x1, wr1);
                ffma2(aC[r], x0, wc0);
                ffma2(aC[r], x1, wc1);
            }
        }
        __syncthreads();   // weights consumed; safe to overwrite next chunk / P
    }

    // write per-warp partials: P[(w*2+arr)*16 + r][64]
#pragma unroll
    for (int r = 0; r < 16; r++) {
        *(ull*)(P + ((w * 2 + 0) * 16 + r) * E_ + 2 * f2) = aR[r];
        *(ull*)(P + ((w * 2 + 1) * 16 + r) * E_ + 2 * f2) = aC[r];
    }
    __syncthreads();

    // remap: thread = (row, fq); sum 8 warp-partials, then stats over 16 lanes
    int row = tid >> 4;
    int fq  = tid & 15;
    float4 R4 = make_float4(0.f, 0.f, 0.f, 0.f);
    float4 C4 = make_float4(0.f, 0.f, 0.f, 0.f);
#pragma unroll
    for (int ww = 0; ww < 8; ww++) {
        float4 pr = *(const float4*)(P + ((ww * 2 + 0) * 16 + row) * E_ + fq * 4);
        float4 pc = *(const float4*)(P + ((ww * 2 + 1) * 16 + row) * E_ + fq * 4);
        R4.x += pr.x; R4.y += pr.y; R4.z += pr.z; R4.w += pr.w;
        C4.x += pc.x; C4.y += pc.y; C4.z += pc.z; C4.w += pc.w;
    }
    float sR  = R4.x + R4.y + R4.z + R4.w;
    float sRR = R4.x * R4.x + R4.y * R4.y + R4.z * R4.z + R4.w * R4.w;
    float sC  = C4.x + C4.y + C4.z + C4.w;
    float sCC = C4.x * C4.x + C4.y * C4.y + C4.z * C4.z + C4.w * C4.w;
#pragma unroll
    for (int o = 1; o < 16; o <<= 1) {
        sR  += __shfl_xor_sync(0xffffffffu, sR,  o);
        sRR += __shfl_xor_sync(0xffffffffu, sRR, o);
        sC  += __shfl_xor_sync(0xffffffffu, sC,  o);
        sCC += __shfl_xor_sync(0xffffffffu, sCC, o);
    }
    float mR = sR * (1.f / 64.f);
    float mC = sC * (1.f / 64.f);
    int grow = row0 + row;
    float4 oR = make_float4(R4.x - mR, R4.y - mR, R4.z - mR, R4.w - mR);
    float4 oC = make_float4(C4.x - mC, C4.y - mC, C4.z - mC, C4.w - mC);
    *(float4*)(g_Rc + grow * E_ + fq * 4) = oR;
    *(float4*)(g_Cc + grow * E_ + fq * 4) = oC;
    if (fq == 0) {
        g_varR[grow] = sRR * (1.f / 64.f) - mR * mR;
        g_varC[grow] = sCC * (1.f / 64.f) - mC * mC;
    }
}

// ---------------- kernel C: dots -> inv-std, then lean streaming stores ------
// grid (48,48,2), block 256, tile 16x16.
__global__ void __launch_bounds__(256, 4) kC(const float* __restrict__ gamma,
                                             const float* __restrict__ beta,
                                             float* __restrict__ out) {
    __shared__ float rs[16 * PADR];    // raw R'
    __shared__ float cs[16 * PADR];    // raw C' (for dots)
    __shared__ float csg[16 * PADR];   // C' * gamma (for stores)
    __shared__ float vR[16];
    __shared__ float vC[16];
    __shared__ float inv[256];

    int i0 = blockIdx.x * 16;
    int j0 = blockIdx.y * 16;
    int b  = blockIdx.z;
    int tid = threadIdx.x;
    int rowR = b * N_ + i0;
    int rowC = b * N_ + j0;

    for (int idx = tid; idx < 16 * E_; idx += 256) {
        int r = idx >> 6, f = idx & 63;
        float cv = g_Cc[(rowC + r) * E_ + f];
        rs[r * PADR + f]  = g_Rc[(rowR + r) * E_ + f];
        cs[r * PADR + f]  = cv;
        csg[r * PADR + f] = cv * __ldg(gamma + f);
    }
    if (tid < 16)      vR[tid]      = g_varR[rowR + tid];
    else if (tid < 32) vC[tid - 16] = g_varC[rowC + tid - 16];
    __syncthreads();

    // ---- Phase A: one 64-wide dot per thread -> inv std ----
    {
        int ii = tid >> 4, jj = tid & 15;
        const float4* r4 = (const float4*)(rs + ii * PADR);
        const float4* c4 = (const float4*)(cs + jj * PADR);
        float d = 0.f;
#pragma unroll
        for (int k = 0; k < 16; k++) {
            float4 a = r4[k], c = c4[k];
            d = fmaf(a.x, c.x, d);
            d = fmaf(a.y, c.y, d);
            d = fmaf(a.z, c.z, d);
            d = fmaf(a.w, c.w, d);
        }
        float var = vR[ii] + vC[jj] + d * (2.f / 64.f);
        inv[tid] = rsqrtf(var + LN_EPS);
    }
    __syncthreads();

    // ---- Phase B: streaming stores, no SHFL/MUFU, iv's in registers ----
    int f4 = tid & 15;
    int g  = tid >> 4;
    float4 gm = __ldg((const float4*)gamma + f4);
    float4 bt = __ldg((const float4*)beta + f4);
    float4 r  = ((const float4*)(rs + g * PADR))[f4];
    float4 u;                                   // u = r' * gamma
    u.x = r.x * gm.x; u.y = r.y * gm.y; u.z = r.z * gm.z; u.w = r.w * gm.w;

    const float4* ivp = (const float4*)(inv + g * 16);
    float4 iva = ivp[0], ivb = ivp[1], ivc = ivp[2], ivd = ivp[3];
    float ivs[16] = {iva.x, iva.y, iva.z, iva.w, ivb.x, ivb.y, ivb.z, ivb.w,
                     ivc.x, ivc.y, ivc.z, ivc.w, ivd.x, ivd.y, ivd.z, ivd.w};

    float4* op = (float4*)out + ((size_t)(b * N_ + i0 + g) * N_ + j0) * 16 + f4;

#pragma unroll
    for (int jj = 0; jj < 16; jj++) {
        float4 v = ((const float4*)(csg + jj * PADR))[f4];
        float iv = ivs[jj];
        float4 o;
        o.x = fmaf(u.x + v.x, iv, bt.x);
        o.y = fmaf(u.y + v.y, iv, bt.y);
        o.z = fmaf(u.z + v.z, iv, bt.z);
        o.w = fmaf(u.w + v.w, iv, bt.w);
        __stcs(op + (size_t)jj * 16, o);
    }
}

// ---------------- launch -------------------------------------------------------
extern "C" void kernel_launch(void* const* d_in, const int* in_sizes, int n_in,
                              void* d_out, int out_size) {
    const float* x     = (const float*)d_in[0];  // [2,768,512]
    const float* Wr    = (const float*)d_in[1];  // [64,512]
    const float* Wc    = (const float*)d_in[2];  // [64,512]
    const float* We    = (const float*)d_in[3];  // [64,64]
    const float* gamma = (const float*)d_in[4];  // [64]
    const float* beta  = (const float*)d_in[5];  // [64]
    float* out = (float*)d_out;                  // [2,768,768,64] fp32

    static int smem_set = 0;
    if (!smem_set) {
        cudaFuncSetAttribute(kB, cudaFuncAttributeMaxDynamicSharedMemorySize, 73856);
        smem_set = 1;
    }

    kA<<<256, 128>>>(We, Wr, Wc);
    kB<<<96, 256, 73856>>>(x);
    kC<<<dim3(N_ / 16, N_ / 16, B_), 256>>>(gamma, beta, out);
}